// round 2
// baseline (speedup 1.0000x reference)
#include <cuda_runtime.h>

// Problem constants
#define N_NODES 4096
#define F_IN    256
#define F_OUT   256
#define H_HEADS 4
#define D_HEAD  64
#define C_OUT   256   // H_HEADS * D_HEAD

#define JSPLIT  2
#define TI      64
#define TJ      16

// ---------------- scratch (no cudaMalloc allowed) ----------------
__device__ __align__(16) float g_h [N_NODES * F_OUT];          // projected features
__device__ __align__(16) float g_S [N_NODES * H_HEADS];        // attn_src
__device__ __align__(16) float g_T [N_NODES * H_HEADS];        // attn_dst
__device__ __align__(16) float g_F1[N_NODES * H_HEADS];        // exp(asrc)
__device__ __align__(16) float g_F2[N_NODES * H_HEADS];        // exp(0.2*asrc)
__device__ __align__(16) float g_E1[N_NODES * H_HEADS];        // exp(adst)
__device__ __align__(16) float g_E2[N_NODES * H_HEADS];        // exp(0.2*adst)
__device__ __align__(16) float g_U [JSPLIT][N_NODES * C_OUT];  // partial weighted sums
__device__ __align__(16) float g_Z [JSPLIT][N_NODES * H_HEADS];// partial softmax denominators

// ---------------- packed f32x2 helpers ----------------
__device__ __forceinline__ void fma2(unsigned long long& acc,
                                     unsigned long long a,
                                     unsigned long long b) {
    asm("fma.rn.f32x2 %0, %1, %2, %0;" : "+l"(acc) : "l"(a), "l"(b));
}
__device__ __forceinline__ unsigned long long pack2(float lo, float hi) {
    unsigned long long r;
    asm("mov.b64 %0, {%1, %2};" : "=l"(r) : "f"(lo), "f"(hi));
    return r;
}
__device__ __forceinline__ void unpack2(unsigned long long v, float& lo, float& hi) {
    asm("mov.b64 {%0, %1}, %2;" : "=f"(lo), "=f"(hi) : "l"(v));
}

// ================= K1: h = x @ W^T  (4096x256x256) =================
__global__ void __launch_bounds__(256) k1_gemm(const float* __restrict__ x,
                                               const float* __restrict__ W) {
    __shared__ float xs[16][68];
    __shared__ float ws[16][68];
    const int tid = threadIdx.x;
    const int m0 = blockIdx.x * 64;
    const int n0 = blockIdx.y * 64;
    const int tr = tid >> 4;      // 0..15
    const int tc = tid & 15;      // 0..15
    const int lm  = tid >> 2;     // 0..63  (stage row)
    const int lk4 = (tid & 3) << 2;

    float acc[4][4];
#pragma unroll
    for (int r = 0; r < 4; r++)
#pragma unroll
        for (int c = 0; c < 4; c++) acc[r][c] = 0.f;

    for (int k0 = 0; k0 < F_IN; k0 += 16) {
        float4 xv = *(const float4*)(x + (size_t)(m0 + lm) * F_IN + k0 + lk4);
        float4 wv = *(const float4*)(W + (size_t)(n0 + lm) * F_IN + k0 + lk4);
        __syncthreads();
        xs[lk4 + 0][lm] = xv.x; xs[lk4 + 1][lm] = xv.y;
        xs[lk4 + 2][lm] = xv.z; xs[lk4 + 3][lm] = xv.w;
        ws[lk4 + 0][lm] = wv.x; ws[lk4 + 1][lm] = wv.y;
        ws[lk4 + 2][lm] = wv.z; ws[lk4 + 3][lm] = wv.w;
        __syncthreads();
#pragma unroll
        for (int kk = 0; kk < 16; kk++) {
            float xa[4], wb[4];
#pragma unroll
            for (int r = 0; r < 4; r++) xa[r] = xs[kk][tr * 4 + r];
#pragma unroll
            for (int c = 0; c < 4; c++) wb[c] = ws[kk][tc * 4 + c];
#pragma unroll
            for (int r = 0; r < 4; r++)
#pragma unroll
                for (int c = 0; c < 4; c++) acc[r][c] += xa[r] * wb[c];
        }
    }
#pragma unroll
    for (int r = 0; r < 4; r++) {
        float4 o = make_float4(acc[r][0], acc[r][1], acc[r][2], acc[r][3]);
        *(float4*)(g_h + (size_t)(m0 + tr * 4 + r) * F_OUT + n0 + tc * 4) = o;
    }
}

// ============ K2: per-node logits + exp factor tables ============
__global__ void __launch_bounds__(256) k2_logits(const float* __restrict__ a_src,
                                                 const float* __restrict__ a_dst) {
    const int idx = blockIdx.x * 256 + threadIdx.x;   // 0..16383
    const int n  = idx >> 2;
    const int hh = idx & 3;
    const float* hp = g_h + (size_t)n * C_OUT + hh * D_HEAD;
    const float* as = a_src + hh * D_HEAD;
    const float* ad = a_dst + hh * D_HEAD;
    float s = 0.f, t = 0.f;
#pragma unroll
    for (int d = 0; d < D_HEAD; d += 4) {
        float4 hv = *(const float4*)(hp + d);
        float4 av = *(const float4*)(as + d);
        float4 dv = *(const float4*)(ad + d);
        s += hv.x * av.x + hv.y * av.y + hv.z * av.z + hv.w * av.w;
        t += hv.x * dv.x + hv.y * dv.y + hv.z * dv.z + hv.w * dv.w;
    }
    g_S[idx]  = s;
    g_T[idx]  = t;
    g_F1[idx] = expf(s);
    g_F2[idx] = expf(0.2f * s);
    g_E1[idx] = expf(t);
    g_E2[idx] = expf(0.2f * t);
}

// ======= K3: fused masked-softmax-weight + aggregation (single adj pass) =======
// CTA: TI=64 rows i, all 256 output cols, j-range = N/JSPLIT.
// Accumulates U[i,c] (unnormalized) and Z[i,h] simultaneously.
__global__ void __launch_bounds__(256, 1) k3_agg(const float* __restrict__ adj) {
    __shared__ __align__(16) float hs [TJ * 256];      // permuted h tile
    __shared__ __align__(16) float wsm[TJ * 256];      // [jj][h*64 + i]
    __shared__ float adj_s[TI][TJ + 1];
    __shared__ float Ts [TJ][4];
    __shared__ float E1s[TJ][4];
    __shared__ float E2s[TJ][4];

    const int tid = threadIdx.x;
    const int i0 = blockIdx.x * TI;
    const int split = blockIdx.y;
    const int jbeg = split * (N_NODES / JSPLIT);
    const int jend = jbeg + (N_NODES / JSPLIT);

    // --- weight-compute role: thread -> (i = tid&63, h = tid>>6) ---
    const int hw = tid >> 6;
    const int iw = tid & 63;
    const float S_i  = g_S [(i0 + iw) * 4 + hw];
    const float F1_i = g_F1[(i0 + iw) * 4 + hw];
    const float F2_i = g_F2[(i0 + iw) * 4 + hw];
    float Zreg = 0.f;

    // --- FMA role: thread -> rows [tr*8..+7], cols [tc*8..+7] ---
    const int tr = tid >> 5;       // 0..7
    const int tc = tid & 31;       // 0..31
    const int hc = tc >> 3;        // head of this col block

    unsigned long long acc[8][4];
#pragma unroll
    for (int r = 0; r < 8; r++)
#pragma unroll
        for (int p = 0; p < 4; p++) acc[r][p] = 0ull;

    const int ar = tid >> 2;           // adj stage row 0..63
    const int ac = (tid & 3) << 2;     // adj stage col 0,4,8,12

    for (int jb = jbeg; jb < jend; jb += TJ) {
        __syncthreads();   // previous tile fully consumed

        // stage adj tile [64][16]
        {
            float4 av = *(const float4*)(adj + (size_t)(i0 + ar) * N_NODES + jb + ac);
            adj_s[ar][ac + 0] = av.x; adj_s[ar][ac + 1] = av.y;
            adj_s[ar][ac + 2] = av.z; adj_s[ar][ac + 3] = av.w;
        }
        // stage per-j exp tables
        if (tid < 64) {
            const int jj = tid >> 2, h2 = tid & 3;
            const int gi = (jb + jj) * 4 + h2;
            Ts [jj][h2] = g_T [gi];
            E1s[jj][h2] = g_E1[gi];
            E2s[jj][h2] = g_E2[gi];
        }
        // stage h tile with lo/hi split layout (conflict-free LDS.128 reads)
#pragma unroll
        for (int it = 0; it < 4; it++) {
            const int lin = it * 1024 + tid * 4;
            const int jj = lin >> 8;
            const int c  = lin & 255;
            float4 hv = *(const float4*)(g_h + (size_t)(jb + jj) * C_OUT + c);
            const int off = jj * 256 + ((c >> 2) & 1) * 128 + (c >> 3) * 4;
            *(float4*)(hs + off) = hv;
        }
        __syncthreads();

        // compute masked softmax weights w = adj * p, accumulate Z = sum p
#pragma unroll
        for (int jj = 0; jj < TJ; jj++) {
            const float t = S_i + Ts[jj][hw];
            const float p = (t >= 0.f) ? F1_i * E1s[jj][hw] : F2_i * E2s[jj][hw];
            const float a = adj_s[iw][jj];
            float w = 0.f;
            if (a > 0.f) { Zreg += p; w = a * p; }
            wsm[jj * 256 + hw * 64 + iw] = w;
        }
        __syncthreads();

        // outer-product accumulation: U[i, c] += w[i] * h[j, c]
#pragma unroll
        for (int jj = 0; jj < TJ; jj++) {
            const ulonglong2 hlo = *(const ulonglong2*)(hs + jj * 256 + tc * 4);
            const ulonglong2 hhi = *(const ulonglong2*)(hs + jj * 256 + 128 + tc * 4);
            const float4 w0 = *(const float4*)(wsm + jj * 256 + hc * 64 + tr * 8);
            const float4 w1 = *(const float4*)(wsm + jj * 256 + hc * 64 + tr * 8 + 4);
            const float wv[8] = {w0.x, w0.y, w0.z, w0.w, w1.x, w1.y, w1.z, w1.w};
#pragma unroll
            for (int r = 0; r < 8; r++) {
                const unsigned long long wp = pack2(wv[r], wv[r]);
                fma2(acc[r][0], wp, hlo.x);
                fma2(acc[r][1], wp, hlo.y);
                fma2(acc[r][2], wp, hhi.x);
                fma2(acc[r][3], wp, hhi.y);
            }
        }
    }

    // write partial Z and U
    g_Z[split][(i0 + iw) * 4 + hw] = Zreg;
#pragma unroll
    for (int r = 0; r < 8; r++) {
        const int row = i0 + tr * 8 + r;
        float a0, a1, a2, a3, a4, a5, a6, a7;
        unpack2(acc[r][0], a0, a1);
        unpack2(acc[r][1], a2, a3);
        unpack2(acc[r][2], a4, a5);
        unpack2(acc[r][3], a6, a7);
        *(float4*)(g_U[split] + (size_t)row * C_OUT + tc * 8)     = make_float4(a0, a1, a2, a3);
        *(float4*)(g_U[split] + (size_t)row * C_OUT + tc * 8 + 4) = make_float4(a4, a5, a6, a7);
    }
}

// ============ K4: reduce splits + normalize (+ nan_to_num) ============
__global__ void __launch_bounds__(256) k4_final(float* __restrict__ out) {
    const int n = blockIdx.x;
    const int c = threadIdx.x;
    const int hh = c >> 6;
    const float Z = g_Z[0][n * 4 + hh] + g_Z[1][n * 4 + hh];
    const float u = g_U[0][n * C_OUT + c] + g_U[1][n * C_OUT + c];
    out[n * C_OUT + c] = (Z > 0.f) ? (u / Z) : 0.f;
}

// ---------------- launch ----------------
extern "C" void kernel_launch(void* const* d_in, const int* in_sizes, int n_in,
                              void* d_out, int out_size) {
    const float* x     = (const float*)d_in[0];
    const float* adj   = (const float*)d_in[1];
    const float* W     = (const float*)d_in[2];
    const float* a_src = (const float*)d_in[3];
    const float* a_dst = (const float*)d_in[4];
    float* out = (float*)d_out;

    k1_gemm<<<dim3(N_NODES / 64, F_OUT / 64), 256>>>(x, W);
    k2_logits<<<(N_NODES * H_HEADS) / 256, 256>>>(a_src, a_dst);
    k3_agg<<<dim3(N_NODES / TI, JSPLIT), 256>>>(adj);
    k4_final<<<N_NODES, 256>>>(out);
}

// round 7
// speedup vs baseline: 1.6162x; 1.6162x over previous
#include <cuda_runtime.h>
#include <cuda_bf16.h>
#include <cstdint>

// Problem constants
#define N_NODES 4096
#define F_IN    256
#define F_OUT   256
#define H_HEADS 4
#define D_HEAD  64
#define C_OUT   256

#define JSPLIT  2
#define JRANGE  (N_NODES / JSPLIT)   // 2048 per CTA

// ---------------- scratch (no cudaMalloc allowed) ----------------
__device__ __align__(16) float g_h  [N_NODES * F_OUT];
__device__ __align__(16) float g_S  [N_NODES * H_HEADS];      // [n*4+h]
__device__ __align__(16) float g_F1 [N_NODES * H_HEADS];
__device__ __align__(16) float g_F2 [N_NODES * H_HEADS];
__device__ __align__(16) float g_Tt [H_HEADS * N_NODES];      // [h][n]
__device__ __align__(16) float2 g_E12t[H_HEADS * N_NODES];    // [h][n] = {E1, E2}
__device__ __align__(16) unsigned short g_hT_hi[C_OUT * N_NODES]; // bf16 [c][n]
__device__ __align__(16) unsigned short g_hT_lo[C_OUT * N_NODES];
__device__ __align__(16) float g_U [JSPLIT][N_NODES * C_OUT];
__device__ __align__(16) float g_Z [JSPLIT][N_NODES * H_HEADS];

// ---------------- mma.sync helper (sm_80+ portable HMMA) ----------------
__device__ __forceinline__ void mma16816(float* c, const uint32_t* a,
                                         uint32_t b0, uint32_t b1) {
    asm volatile(
        "mma.sync.aligned.m16n8k16.row.col.f32.bf16.bf16.f32 "
        "{%0,%1,%2,%3}, {%4,%5,%6,%7}, {%8,%9}, {%0,%1,%2,%3};"
        : "+f"(c[0]), "+f"(c[1]), "+f"(c[2]), "+f"(c[3])
        : "r"(a[0]), "r"(a[1]), "r"(a[2]), "r"(a[3]), "r"(b0), "r"(b1));
}

// ================= K1: h = x @ W^T  (4096x256x256) =================
__global__ void __launch_bounds__(256) k1_gemm(const float* __restrict__ x,
                                               const float* __restrict__ W) {
    __shared__ float xs[16][68];
    __shared__ float ws[16][68];
    const int tid = threadIdx.x;
    const int m0 = blockIdx.x * 64;
    const int n0 = blockIdx.y * 64;
    const int tr = tid >> 4, tc = tid & 15;
    const int lm = tid >> 2, lk4 = (tid & 3) << 2;

    float acc[4][4];
#pragma unroll
    for (int r = 0; r < 4; r++)
#pragma unroll
        for (int c = 0; c < 4; c++) acc[r][c] = 0.f;

    for (int k0 = 0; k0 < F_IN; k0 += 16) {
        float4 xv = *(const float4*)(x + (size_t)(m0 + lm) * F_IN + k0 + lk4);
        float4 wv = *(const float4*)(W + (size_t)(n0 + lm) * F_IN + k0 + lk4);
        __syncthreads();
        xs[lk4 + 0][lm] = xv.x; xs[lk4 + 1][lm] = xv.y;
        xs[lk4 + 2][lm] = xv.z; xs[lk4 + 3][lm] = xv.w;
        ws[lk4 + 0][lm] = wv.x; ws[lk4 + 1][lm] = wv.y;
        ws[lk4 + 2][lm] = wv.z; ws[lk4 + 3][lm] = wv.w;
        __syncthreads();
#pragma unroll
        for (int kk = 0; kk < 16; kk++) {
            float xa[4], wb[4];
#pragma unroll
            for (int r = 0; r < 4; r++) xa[r] = xs[kk][tr * 4 + r];
#pragma unroll
            for (int c = 0; c < 4; c++) wb[c] = ws[kk][tc * 4 + c];
#pragma unroll
            for (int r = 0; r < 4; r++)
#pragma unroll
                for (int c = 0; c < 4; c++) acc[r][c] += xa[r] * wb[c];
        }
    }
#pragma unroll
    for (int r = 0; r < 4; r++)
        *(float4*)(g_h + (size_t)(m0 + tr * 4 + r) * F_OUT + n0 + tc * 4) =
            make_float4(acc[r][0], acc[r][1], acc[r][2], acc[r][3]);
}

// ============ K2: per-node logits + exp factor tables ============
__global__ void __launch_bounds__(256) k2_logits(const float* __restrict__ a_src,
                                                 const float* __restrict__ a_dst) {
    const int idx = blockIdx.x * 256 + threadIdx.x;
    const int n  = idx >> 2;
    const int hh = idx & 3;
    const float* hp = g_h + (size_t)n * C_OUT + hh * D_HEAD;
    const float* as = a_src + hh * D_HEAD;
    const float* ad = a_dst + hh * D_HEAD;
    float s = 0.f, t = 0.f;
#pragma unroll
    for (int d = 0; d < D_HEAD; d += 4) {
        float4 hv = *(const float4*)(hp + d);
        float4 av = *(const float4*)(as + d);
        float4 dv = *(const float4*)(ad + d);
        s += hv.x * av.x + hv.y * av.y + hv.z * av.z + hv.w * av.w;
        t += hv.x * dv.x + hv.y * dv.y + hv.z * dv.z + hv.w * dv.w;
    }
    g_S [idx] = s;
    g_F1[idx] = expf(s);
    g_F2[idx] = expf(0.2f * s);
    g_Tt  [hh * N_NODES + n] = t;
    g_E12t[hh * N_NODES + n] = make_float2(expf(t), expf(0.2f * t));
}

// ============ K2b: transpose h -> bf16 hi/lo [c][n] ============
__global__ void __launch_bounds__(256) k2b_transpose() {
    __shared__ float ts[32][33];
    const int tid = threadIdx.x;
    const int tx = tid & 31, ty = tid >> 5;
    const int n0 = blockIdx.x * 32;
    const int c0 = blockIdx.y * 32;
#pragma unroll
    for (int k = 0; k < 4; k++)
        ts[ty + 8 * k][tx] = g_h[(size_t)(n0 + ty + 8 * k) * C_OUT + c0 + tx];
    __syncthreads();
#pragma unroll
    for (int k = 0; k < 4; k++) {
        const int cl = ty + 8 * k;
        const float v = ts[tx][cl];
        const uint32_t u = __float_as_uint(v);
        const float lo_f = v - __uint_as_float(u & 0xffff0000u);
        __nv_bfloat16 lb = __float2bfloat16_rn(lo_f);
        const size_t o = (size_t)(c0 + cl) * N_NODES + n0 + tx;
        g_hT_hi[o] = (unsigned short)(u >> 16);
        g_hT_lo[o] = *reinterpret_cast<unsigned short*>(&lb);
    }
}

// ---- weight for one (i, j): factored-exp masked softmax term ----
__device__ __forceinline__ float gat_w(float S, float F1, float F2,
                                       float T, float E1, float E2,
                                       float a, float& Z) {
    const float t = S + T;
    const float p = (t >= 0.f) ? F1 * E1 : F2 * E2;
    float w = 0.f;
    if (a > 0.f) { Z += p; w = a * p; }
    return w;
}

// ======= K3: fused masked-softmax + aggregation via mma.sync (HMMA) =======
// Warp tile: 32 rows x 64 cols (one head). CTA: 128 rows x 128 cols (2 heads).
// Grid: (32 i-tiles, 2 head-pairs, JSPLIT).
__global__ void __launch_bounds__(256, 1) k3_agg(const float* __restrict__ adj) {
    const int tid  = threadIdx.x;
    const int wid  = tid >> 5;
    const int lane = tid & 31;
    const int i0   = blockIdx.x * 128;
    const int hp   = blockIdx.y;
    const int js   = blockIdx.z;
    const int rg   = wid >> 1;                 // row group 0..3
    const int h    = hp * 2 + (wid & 1);       // head for this warp
    const int m    = lane & 3;                 // quad index -> k offset
    const int rbase = i0 + rg * 32 + (lane >> 2);
    const int jbeg = js * JRANGE;

    // per-row constants (rows rbase + {0,8,16,24})
    float S[4], F1[4], F2[4], Z[4];
#pragma unroll
    for (int r4 = 0; r4 < 4; r4++) {
        const int idx = (rbase + r4 * 8) * H_HEADS + h;
        S[r4] = g_S[idx]; F1[r4] = g_F1[idx]; F2[r4] = g_F2[idx];
        Z[r4] = 0.f;
    }
    const float* adjp[4];
#pragma unroll
    for (int r4 = 0; r4 < 4; r4++)
        adjp[r4] = adj + (size_t)(rbase + r4 * 8) * N_NODES + jbeg;

    const float*  Tp = g_Tt + h * N_NODES + jbeg;
    const float2* Ep = g_E12t + h * N_NODES + jbeg;
    const unsigned short* Bhi = g_hT_hi + (size_t)(h * 64 + (lane >> 2)) * N_NODES + jbeg;
    const unsigned short* Blo = g_hT_lo + (size_t)(h * 64 + (lane >> 2)) * N_NODES + jbeg;

    float acc[2][8][4];
#pragma unroll
    for (int mt = 0; mt < 2; mt++)
#pragma unroll
        for (int nt = 0; nt < 8; nt++)
#pragma unroll
            for (int q = 0; q < 4; q++) acc[mt][nt][q] = 0.f;

#pragma unroll 1
    for (int jb = 0; jb < JRANGE; jb += 16) {
        const int k0 = jb + 2 * m;            // even
        // per-j tables (broadcast within quad via L1)
        const float2 T01 = *(const float2*)(Tp + k0);
        const float2 T89 = *(const float2*)(Tp + k0 + 8);
        const float4 Ea  = *(const float4*)(Ep + k0);      // E1,E2 for k0, k0+1
        const float4 Eb  = *(const float4*)(Ep + k0 + 8);  // E1,E2 for k0+8, k0+9

        // A fragments: compute weights directly in fragment layout
        uint32_t ahi[2][4], alo[2][4];
#pragma unroll
        for (int mt = 0; mt < 2; mt++) {
#pragma unroll
            for (int hf = 0; hf < 2; hf++) {
                const int r4 = mt * 2 + hf;
                const float2 aA = *(const float2*)(adjp[r4] + k0);
                const float2 aB = *(const float2*)(adjp[r4] + k0 + 8);
                const float w0 = gat_w(S[r4], F1[r4], F2[r4], T01.x, Ea.x, Ea.y, aA.x, Z[r4]);
                const float w1 = gat_w(S[r4], F1[r4], F2[r4], T01.y, Ea.z, Ea.w, aA.y, Z[r4]);
                const float w2 = gat_w(S[r4], F1[r4], F2[r4], T89.x, Eb.x, Eb.y, aB.x, Z[r4]);
                const float w3 = gat_w(S[r4], F1[r4], F2[r4], T89.y, Eb.z, Eb.w, aB.y, Z[r4]);
                const uint32_t u0 = __float_as_uint(w0), u1 = __float_as_uint(w1);
                const uint32_t u2 = __float_as_uint(w2), u3 = __float_as_uint(w3);
                ahi[mt][hf]     = (u0 >> 16) | (u1 & 0xffff0000u);   // k0 pair
                ahi[mt][2 + hf] = (u2 >> 16) | (u3 & 0xffff0000u);   // k0+8 pair
                const float l0 = w0 - __uint_as_float(u0 & 0xffff0000u);
                const float l1 = w1 - __uint_as_float(u1 & 0xffff0000u);
                const float l2 = w2 - __uint_as_float(u2 & 0xffff0000u);
                const float l3 = w3 - __uint_as_float(u3 & 0xffff0000u);
                __nv_bfloat162 p01 = __floats2bfloat162_rn(l0, l1);
                __nv_bfloat162 p23 = __floats2bfloat162_rn(l2, l3);
                alo[mt][hf]     = *reinterpret_cast<uint32_t*>(&p01);
                alo[mt][2 + hf] = *reinterpret_cast<uint32_t*>(&p23);
            }
        }

        // B fragments + 3-product split MMAs (hi*hi + hi*lo + lo*hi)
#pragma unroll
        for (int nt = 0; nt < 8; nt++) {
            const size_t bo = (size_t)nt * 8 * N_NODES + k0;
            const uint32_t bh0 = *(const uint32_t*)(Bhi + bo);
            const uint32_t bh1 = *(const uint32_t*)(Bhi + bo + 8);
            const uint32_t bl0 = *(const uint32_t*)(Blo + bo);
            const uint32_t bl1 = *(const uint32_t*)(Blo + bo + 8);
#pragma unroll
            for (int mt = 0; mt < 2; mt++) {
                mma16816(acc[mt][nt], ahi[mt], bh0, bh1);
                mma16816(acc[mt][nt], ahi[mt], bl0, bl1);
                mma16816(acc[mt][nt], alo[mt], bh0, bh1);
            }
        }
    }

    // Z: reduce over the 4 lanes of each quad (they cover disjoint j)
#pragma unroll
    for (int r4 = 0; r4 < 4; r4++) {
        Z[r4] += __shfl_xor_sync(0xffffffffu, Z[r4], 1);
        Z[r4] += __shfl_xor_sync(0xffffffffu, Z[r4], 2);
    }
    if (m == 0) {
#pragma unroll
        for (int r4 = 0; r4 < 4; r4++)
            g_Z[js][(rbase + r4 * 8) * H_HEADS + h] = Z[r4];
    }

    // U partial store
#pragma unroll
    for (int mt = 0; mt < 2; mt++) {
        const int row_lo = i0 + rg * 32 + mt * 16 + (lane >> 2);
        const int row_hi = row_lo + 8;
#pragma unroll
        for (int nt = 0; nt < 8; nt++) {
            const int col = h * 64 + nt * 8 + 2 * m;
            *(float2*)(g_U[js] + (size_t)row_lo * C_OUT + col) =
                make_float2(acc[mt][nt][0], acc[mt][nt][1]);
            *(float2*)(g_U[js] + (size_t)row_hi * C_OUT + col) =
                make_float2(acc[mt][nt][2], acc[mt][nt][3]);
        }
    }
}

// ============ K4: reduce splits + normalize (+ nan_to_num) ============
__global__ void __launch_bounds__(256) k4_final(float* __restrict__ out) {
    const int idx = blockIdx.x * 256 + threadIdx.x;   // one float4 each
    const int n  = idx >> 6;
    const int c4 = (idx & 63) * 4;
    const int hh = c4 >> 6;
    float Z = 0.f;
#pragma unroll
    for (int s = 0; s < JSPLIT; s++) Z += g_Z[s][n * H_HEADS + hh];
    float4 u = make_float4(0.f, 0.f, 0.f, 0.f);
#pragma unroll
    for (int s = 0; s < JSPLIT; s++) {
        float4 v = *(const float4*)(g_U[s] + (size_t)n * C_OUT + c4);
        u.x += v.x; u.y += v.y; u.z += v.z; u.w += v.w;
    }
    const float r = (Z > 0.f) ? (1.f / Z) : 0.f;
    *(float4*)(out + (size_t)n * C_OUT + c4) =
        make_float4(u.x * r, u.y * r, u.z * r, u.w * r);
}

// ---------------- launch ----------------
extern "C" void kernel_launch(void* const* d_in, const int* in_sizes, int n_in,
                              void* d_out, int out_size) {
    const float* x     = (const float*)d_in[0];
    const float* adj   = (const float*)d_in[1];
    const float* W     = (const float*)d_in[2];
    const float* a_src = (const float*)d_in[3];
    const float* a_dst = (const float*)d_in[4];
    float* out = (float*)d_out;

    k1_gemm<<<dim3(N_NODES / 64, F_OUT / 64), 256>>>(x, W);
    k2_logits<<<(N_NODES * H_HEADS) / 256, 256>>>(a_src, a_dst);
    k2b_transpose<<<dim3(N_NODES / 32, C_OUT / 32), 256>>>();
    k3_agg<<<dim3(N_NODES / 128, 2, JSPLIT), 256>>>(adj);
    k4_final<<<(N_NODES * C_OUT / 4) / 256, 256>>>(out);
}

// round 8
// speedup vs baseline: 2.0929x; 1.2949x over previous
#include <cuda_runtime.h>
#include <cuda_bf16.h>
#include <cstdint>

// Problem constants
#define N_NODES 4096
#define F_IN    256
#define F_OUT   256
#define H_HEADS 4
#define D_HEAD  64
#define C_OUT   256

#define JSPLIT  2
#define JRANGE  (N_NODES / JSPLIT)   // 2048 per CTA

// ---------------- scratch (no cudaMalloc allowed) ----------------
__device__ __align__(16) float g_h  [N_NODES * F_OUT];
__device__ __align__(16) float g_S  [N_NODES * H_HEADS];      // [n*4+h]
__device__ __align__(16) float g_F1 [N_NODES * H_HEADS];
__device__ __align__(16) float g_F2 [N_NODES * H_HEADS];
__device__ __align__(16) float g_Tt [H_HEADS * N_NODES];      // [h][n]
__device__ __align__(16) float2 g_E12t[H_HEADS * N_NODES];    // [h][n] = {E1, E2}
// fragment-packed B: [h][j16][c8][lane] -> uint4{hi_b0, hi_b1, lo_b0, lo_b1}
__device__ uint4 g_Bpk[H_HEADS * (N_NODES / 16) * 8 * 32];
__device__ __align__(16) float g_U [JSPLIT][N_NODES * C_OUT];
__device__ __align__(16) float g_Z [JSPLIT][N_NODES * H_HEADS];

// ---------------- mma.sync helper (sm_80+ portable HMMA) ----------------
__device__ __forceinline__ void mma16816(float* c, const uint32_t* a,
                                         uint32_t b0, uint32_t b1) {
    asm volatile(
        "mma.sync.aligned.m16n8k16.row.col.f32.bf16.bf16.f32 "
        "{%0,%1,%2,%3}, {%4,%5,%6,%7}, {%8,%9}, {%0,%1,%2,%3};"
        : "+f"(c[0]), "+f"(c[1]), "+f"(c[2]), "+f"(c[3])
        : "r"(a[0]), "r"(a[1]), "r"(a[2]), "r"(a[3]), "r"(b0), "r"(b1));
}

// ================= K1: h = x @ W^T  (4096x256x256) =================
__global__ void __launch_bounds__(256) k1_gemm(const float* __restrict__ x,
                                               const float* __restrict__ W) {
    __shared__ float xs[16][68];
    __shared__ float ws[16][68];
    const int tid = threadIdx.x;
    const int m0 = blockIdx.x * 64;
    const int n0 = blockIdx.y * 64;
    const int tr = tid >> 4, tc = tid & 15;
    const int lm = tid >> 2, lk4 = (tid & 3) << 2;

    float acc[4][4];
#pragma unroll
    for (int r = 0; r < 4; r++)
#pragma unroll
        for (int c = 0; c < 4; c++) acc[r][c] = 0.f;

    for (int k0 = 0; k0 < F_IN; k0 += 16) {
        float4 xv = *(const float4*)(x + (size_t)(m0 + lm) * F_IN + k0 + lk4);
        float4 wv = *(const float4*)(W + (size_t)(n0 + lm) * F_IN + k0 + lk4);
        __syncthreads();
        xs[lk4 + 0][lm] = xv.x; xs[lk4 + 1][lm] = xv.y;
        xs[lk4 + 2][lm] = xv.z; xs[lk4 + 3][lm] = xv.w;
        ws[lk4 + 0][lm] = wv.x; ws[lk4 + 1][lm] = wv.y;
        ws[lk4 + 2][lm] = wv.z; ws[lk4 + 3][lm] = wv.w;
        __syncthreads();
#pragma unroll
        for (int kk = 0; kk < 16; kk++) {
            float xa[4], wb[4];
#pragma unroll
            for (int r = 0; r < 4; r++) xa[r] = xs[kk][tr * 4 + r];
#pragma unroll
            for (int c = 0; c < 4; c++) wb[c] = ws[kk][tc * 4 + c];
#pragma unroll
            for (int r = 0; r < 4; r++)
#pragma unroll
                for (int c = 0; c < 4; c++) acc[r][c] += xa[r] * wb[c];
        }
    }
#pragma unroll
    for (int r = 0; r < 4; r++)
        *(float4*)(g_h + (size_t)(m0 + tr * 4 + r) * F_OUT + n0 + tc * 4) =
            make_float4(acc[r][0], acc[r][1], acc[r][2], acc[r][3]);
}

// ============ K2: per-node logits + exp factor tables ============
__global__ void __launch_bounds__(256) k2_logits(const float* __restrict__ a_src,
                                                 const float* __restrict__ a_dst) {
    const int idx = blockIdx.x * 256 + threadIdx.x;
    const int n  = idx >> 2;
    const int hh = idx & 3;
    const float* hp = g_h + (size_t)n * C_OUT + hh * D_HEAD;
    const float* as = a_src + hh * D_HEAD;
    const float* ad = a_dst + hh * D_HEAD;
    float s = 0.f, t = 0.f;
#pragma unroll
    for (int d = 0; d < D_HEAD; d += 4) {
        float4 hv = *(const float4*)(hp + d);
        float4 av = *(const float4*)(as + d);
        float4 dv = *(const float4*)(ad + d);
        s += hv.x * av.x + hv.y * av.y + hv.z * av.z + hv.w * av.w;
        t += hv.x * dv.x + hv.y * dv.y + hv.z * dv.z + hv.w * dv.w;
    }
    g_S [idx] = s;
    g_F1[idx] = expf(s);
    g_F2[idx] = expf(0.2f * s);
    g_Tt  [hh * N_NODES + n] = t;
    g_E12t[hh * N_NODES + n] = make_float2(expf(t), expf(0.2f * t));
}

// ============ K2b: pack h -> fragment-order bf16 hi/lo B tiles ============
// Output chunk (h, j16, c8): lane l holds uint4 {hi(k0 pair), hi(k0+8 pair),
// lo(k0 pair), lo(k0+8 pair)} for c = c8*8 + (l>>2), k0 = j16*16 + 2*(l&3).
__global__ void __launch_bounds__(256) k2b_pack() {
    __shared__ float ts[32][33];
    const int tid = threadIdx.x;
    const int tx = tid & 31, ty = tid >> 5;
    const int n0 = blockIdx.x * 32;   // j dimension (nodes)
    const int c0 = blockIdx.y * 32;   // feature dimension
#pragma unroll
    for (int k = 0; k < 4; k++)
        ts[ty + 8 * k][tx] = g_h[(size_t)(n0 + ty + 8 * k) * C_OUT + c0 + tx];
    __syncthreads();

    const int lane = tid & 31;
    const int m    = lane & 3;
    const int cr   = lane >> 2;
    const int c8l  = (tid >> 5) & 3;
    const int j16l = tid >> 7;
    const int jl   = j16l * 16 + 2 * m;
    const int cl   = c8l * 8 + cr;

    const float w0 = ts[jl][cl],     w1 = ts[jl + 1][cl];
    const float w8 = ts[jl + 8][cl], w9 = ts[jl + 9][cl];
    const uint32_t u0 = __float_as_uint(w0), u1 = __float_as_uint(w1);
    const uint32_t u8 = __float_as_uint(w8), u9 = __float_as_uint(w9);
    const uint32_t xhi = (u0 >> 16) | (u1 & 0xffff0000u);
    const uint32_t yhi = (u8 >> 16) | (u9 & 0xffff0000u);
    const float l0 = w0 - __uint_as_float(u0 & 0xffff0000u);
    const float l1 = w1 - __uint_as_float(u1 & 0xffff0000u);
    const float l8 = w8 - __uint_as_float(u8 & 0xffff0000u);
    const float l9 = w9 - __uint_as_float(u9 & 0xffff0000u);
    __nv_bfloat162 p01 = __floats2bfloat162_rn(l0, l1);
    __nv_bfloat162 p89 = __floats2bfloat162_rn(l8, l9);

    const int cg  = c0 + cl;
    const int h   = cg >> 6;
    const int c8  = (cg & 63) >> 3;
    const int j16 = (n0 >> 4) + j16l;
    g_Bpk[((h * (N_NODES / 16) + j16) * 8 + c8) * 32 + lane] =
        make_uint4(xhi, yhi, *reinterpret_cast<uint32_t*>(&p01),
                   *reinterpret_cast<uint32_t*>(&p89));
}

// ---- weight for one (i, j): factored-exp masked softmax term ----
__device__ __forceinline__ float gat_w(float S, float F1, float F2,
                                       float T, float E1, float E2,
                                       float a, float& Z) {
    const float t = S + T;
    const float p = (t >= 0.f) ? F1 * E1 : F2 * E2;
    float w = 0.f;
    if (a > 0.f) { Z += p; w = a * p; }
    return w;
}

// ======= K3: fused masked-softmax + aggregation via mma.sync (HMMA) =======
// Warp tile: 32 rows x 64 cols (one head). CTA: 128 rows x 128 cols (2 heads).
// Coalesced adj loads (quad owns 4 j) redistributed into fragment layout by
// quad shfl; B loaded as one LDG.128 per nt from fragment-packed g_Bpk.
__global__ void __launch_bounds__(256, 1) k3_agg(const float* __restrict__ adj) {
    const int tid  = threadIdx.x;
    const int wid  = tid >> 5;
    const int lane = tid & 31;
    const int i0   = blockIdx.x * 128;
    const int hp   = blockIdx.y;
    const int js   = blockIdx.z;
    const int rg   = wid >> 1;
    const int h    = hp * 2 + (wid & 1);
    const int m    = lane & 3;
    const int rbase = i0 + rg * 32 + (lane >> 2);
    const int jbeg  = js * JRANGE;

    float S[4], F1[4], F2[4], Z[4];
    const float* adjp[4];
#pragma unroll
    for (int r4 = 0; r4 < 4; r4++) {
        const int idx = (rbase + r4 * 8) * H_HEADS + h;
        S[r4] = g_S[idx]; F1[r4] = g_F1[idx]; F2[r4] = g_F2[idx];
        Z[r4] = 0.f;
        adjp[r4] = adj + (size_t)(rbase + r4 * 8) * N_NODES + jbeg;
    }
    const float*  Tp  = g_Tt + h * N_NODES + jbeg;
    const float4* Ep4 = (const float4*)(g_E12t + h * N_NODES + jbeg);
    const uint4*  Bbase = g_Bpk + (size_t)(h * (N_NODES / 16) + (jbeg >> 4)) * 8 * 32 + lane;

    float acc[2][8][4];
#pragma unroll
    for (int mt = 0; mt < 2; mt++)
#pragma unroll
        for (int nt = 0; nt < 8; nt++)
#pragma unroll
            for (int q = 0; q < 4; q++) acc[mt][nt][q] = 0.f;

    const int sl0 = (lane & ~3) | (m >> 1);   // quad src lane for k0 pairs
    const int sl1 = sl0 + 2;                  // quad src lane for k0+8 pairs
    const bool odd = (m & 1);

#pragma unroll 1
    for (int jb = 0; jb < JRANGE; jb += 16) {
        // per-j tables for this lane's 4 owned j (jb+4m .. jb+4m+3)
        const float4 T4 = *(const float4*)(Tp + jb + 4 * m);
        const float4 Ea = Ep4[(jb >> 1) + 2 * m];
        const float4 Eb = Ep4[(jb >> 1) + 2 * m + 1];

        uint32_t ahi[2][4], alo[2][4];
#pragma unroll
        for (int r4 = 0; r4 < 4; r4++) {
            const float4 A4 = *(const float4*)(adjp[r4] + jb + 4 * m);
            const float w0 = gat_w(S[r4], F1[r4], F2[r4], T4.x, Ea.x, Ea.y, A4.x, Z[r4]);
            const float w1 = gat_w(S[r4], F1[r4], F2[r4], T4.y, Ea.z, Ea.w, A4.y, Z[r4]);
            const float w2 = gat_w(S[r4], F1[r4], F2[r4], T4.z, Eb.x, Eb.y, A4.z, Z[r4]);
            const float w3 = gat_w(S[r4], F1[r4], F2[r4], T4.w, Eb.z, Eb.w, A4.w, Z[r4]);
            const uint32_t u0 = __float_as_uint(w0), u1 = __float_as_uint(w1);
            const uint32_t u2 = __float_as_uint(w2), u3 = __float_as_uint(w3);
            const uint32_t whiA = (u0 >> 16) | (u1 & 0xffff0000u);  // j pair 4m
            const uint32_t whiB = (u2 >> 16) | (u3 & 0xffff0000u);  // j pair 4m+2
            const float l0 = w0 - __uint_as_float(u0 & 0xffff0000u);
            const float l1 = w1 - __uint_as_float(u1 & 0xffff0000u);
            const float l2 = w2 - __uint_as_float(u2 & 0xffff0000u);
            const float l3 = w3 - __uint_as_float(u3 & 0xffff0000u);
            __nv_bfloat162 pA = __floats2bfloat162_rn(l0, l1);
            __nv_bfloat162 pB = __floats2bfloat162_rn(l2, l3);
            const uint32_t wloA = *reinterpret_cast<const uint32_t*>(&pA);
            const uint32_t wloB = *reinterpret_cast<const uint32_t*>(&pB);

            // redistribute quad-owned pairs into fragment positions
            const uint32_t hA0 = __shfl_sync(0xffffffffu, whiA, sl0);
            const uint32_t hB0 = __shfl_sync(0xffffffffu, whiB, sl0);
            const uint32_t hA1 = __shfl_sync(0xffffffffu, whiA, sl1);
            const uint32_t hB1 = __shfl_sync(0xffffffffu, whiB, sl1);
            const uint32_t lA0 = __shfl_sync(0xffffffffu, wloA, sl0);
            const uint32_t lB0 = __shfl_sync(0xffffffffu, wloB, sl0);
            const uint32_t lA1 = __shfl_sync(0xffffffffu, wloA, sl1);
            const uint32_t lB1 = __shfl_sync(0xffffffffu, wloB, sl1);
            const int mt = r4 >> 1, hf = r4 & 1;
            ahi[mt][hf]     = odd ? hB0 : hA0;
            ahi[mt][2 + hf] = odd ? hB1 : hA1;
            alo[mt][hf]     = odd ? lB0 : lA0;
            alo[mt][2 + hf] = odd ? lB1 : lA1;
        }

        // B fragments (one coalesced LDG.128 per nt) + 3-product split MMAs
        const uint4* Bp = Bbase + (size_t)(jb >> 4) * 8 * 32;
#pragma unroll
        for (int nt = 0; nt < 8; nt++) {
            const uint4 bv = Bp[nt * 32];
#pragma unroll
            for (int mt = 0; mt < 2; mt++) {
                mma16816(acc[mt][nt], ahi[mt], bv.x, bv.y);
                mma16816(acc[mt][nt], ahi[mt], bv.z, bv.w);
                mma16816(acc[mt][nt], alo[mt], bv.x, bv.y);
            }
        }
    }

    // Z: reduce over the 4 lanes of each quad (disjoint j coverage)
#pragma unroll
    for (int r4 = 0; r4 < 4; r4++) {
        Z[r4] += __shfl_xor_sync(0xffffffffu, Z[r4], 1);
        Z[r4] += __shfl_xor_sync(0xffffffffu, Z[r4], 2);
    }
    if (m == 0) {
#pragma unroll
        for (int r4 = 0; r4 < 4; r4++)
            g_Z[js][(rbase + r4 * 8) * H_HEADS + h] = Z[r4];
    }

    // U partial store
#pragma unroll
    for (int mt = 0; mt < 2; mt++) {
        const int row_lo = i0 + rg * 32 + mt * 16 + (lane >> 2);
        const int row_hi = row_lo + 8;
#pragma unroll
        for (int nt = 0; nt < 8; nt++) {
            const int col = h * 64 + nt * 8 + 2 * m;
            *(float2*)(g_U[js] + (size_t)row_lo * C_OUT + col) =
                make_float2(acc[mt][nt][0], acc[mt][nt][1]);
            *(float2*)(g_U[js] + (size_t)row_hi * C_OUT + col) =
                make_float2(acc[mt][nt][2], acc[mt][nt][3]);
        }
    }
}

// ============ K4: reduce splits + normalize (+ nan_to_num) ============
__global__ void __launch_bounds__(256) k4_final(float* __restrict__ out) {
    const int idx = blockIdx.x * 256 + threadIdx.x;   // one float4 each
    const int n  = idx >> 6;
    const int c4 = (idx & 63) * 4;
    const int hh = c4 >> 6;
    float Z = 0.f;
#pragma unroll
    for (int s = 0; s < JSPLIT; s++) Z += g_Z[s][n * H_HEADS + hh];
    float4 u = make_float4(0.f, 0.f, 0.f, 0.f);
#pragma unroll
    for (int s = 0; s < JSPLIT; s++) {
        float4 v = *(const float4*)(g_U[s] + (size_t)n * C_OUT + c4);
        u.x += v.x; u.y += v.y; u.z += v.z; u.w += v.w;
    }
    const float r = (Z > 0.f) ? (1.f / Z) : 0.f;
    *(float4*)(out + (size_t)n * C_OUT + c4) =
        make_float4(u.x * r, u.y * r, u.z * r, u.w * r);
}

// ---------------- launch ----------------
extern "C" void kernel_launch(void* const* d_in, const int* in_sizes, int n_in,
                              void* d_out, int out_size) {
    const float* x     = (const float*)d_in[0];
    const float* adj   = (const float*)d_in[1];
    const float* W     = (const float*)d_in[2];
    const float* a_src = (const float*)d_in[3];
    const float* a_dst = (const float*)d_in[4];
    float* out = (float*)d_out;

    k1_gemm<<<dim3(N_NODES / 64, F_OUT / 64), 256>>>(x, W);
    k2_logits<<<(N_NODES * H_HEADS) / 256, 256>>>(a_src, a_dst);
    k2b_pack<<<dim3(N_NODES / 32, C_OUT / 32), 256>>>();
    k3_agg<<<dim3(N_NODES / 128, 2, JSPLIT), 256>>>(adj);
    k4_final<<<(N_NODES * C_OUT / 4) / 256, 256>>>(out);
}